// round 14
// baseline (speedup 1.0000x reference)
#include <cuda_runtime.h>
#include <math.h>
#include <stdint.h>

#define S 100
#define BATCH 128
#define NW 430500
#define NB 580
#define ES (NW + NB)
#define W12N 25500
#define WOFF2 25500
#define WOFF3 425500

// ---------------- scratch (device globals; no runtime allocation) ----------------
__device__ float g_sigw[NW];
__device__ float g_sigb[NB];
__device__ float g_w1p[S * 1024];         // conv1 weights [kk32][ch32 pad], tf32; pads stay zero
__device__ float g_w2p[S * 33280];        // conv2 weights [k=ci*32+kk][52 ch pad], tf32
__device__ float g_ball[S * NB];          // per-sample all biases
__device__ float g_h1[S * BATCH * 2880];  // after conv1+relu+pool: [s][b][20][12][12]
__device__ float g_h2[S * BATCH * 800];   // after conv2+relu+pool: [s][b][800] (c*16+y*4+x)
__device__ float g_h3[S * 500 * BATCH];   // after fc1+relu: [s][500][128]
__device__ float g_lsm[S * BATCH * 10];   // per-sample log-softmax

__device__ __forceinline__ float softplusf(float r) {
    return fmaxf(r, 0.0f) + log1pf(expf(-fabsf(r)));
}

__device__ __forceinline__ uint32_t f2tf32(float v) {
    uint32_t o;
    asm("cvt.rna.tf32.f32 %0, %1;" : "=r"(o) : "f"(v));
    return o;
}

// ---------------- kernel 0: softplus(rho) ----------------
__global__ void k_sig(const float* __restrict__ rho_w, const float* __restrict__ rho_b) {
    int i = blockIdx.x * blockDim.x + threadIdx.x;
    if (i < NW) g_sigw[i] = softplusf(rho_w[i]);
    else if (i < NW + NB) g_sigb[i - NW] = softplusf(rho_b[i - NW]);
}

// ---------------- kernel 1: materialize conv weights + biases ----------------
// conv1 -> g_w1p [kk*32 + ch] (kk 25..31, ch 20..31 stay zero)
// conv2 -> g_w2p [(ci*32+wo)*52 + ch] (pads stay zero)
__global__ void k_wb(const float* __restrict__ e,
                     const float* __restrict__ mu_w,
                     const float* __restrict__ mu_b) {
    int i = blockIdx.x * blockDim.x + threadIdx.x;
    if (i < S * W12N) {
        int s = i / W12N, j = i % W12N;
        float v = fmaf(g_sigw[j], e[(long)s * ES + j], mu_w[j]);
        if (j < 500) {
            int ch = j / 25, wo = j % 25;
            g_w1p[s * 1024 + wo * 32 + ch] = __uint_as_float(f2tf32(v));
        } else {
            int jj = j - 500;
            int ch = jj / 500;
            int r = jj % 500;
            int ci = r / 25, wo = r % 25;
            g_w2p[(long)s * 33280 + (ci * 32 + wo) * 52 + ch] = __uint_as_float(f2tf32(v));
        }
    } else {
        int r = i - S * W12N;
        if (r < S * NB) {
            int s = r / NB, j = r % NB;
            g_ball[r] = fmaf(g_sigb[j], e[(long)s * ES + NW + j], mu_b[j]);
        }
    }
}

// ---------------- kernel 2: conv1 tf32 implicit GEMM, direct B gather ----------------
// One block = (sample, image), 288 threads / 9 warps, warp tile m32 x n64.
// C[32][576] = W1[32][32] x im2col[32][576]; K=25 padded to 32 (zero weight rows).
// B gathered straight from x tile in smem; no syncs in the mainloop.
// smem union: mainloop xs(784)+W(1056) | epilogue C[20][584] -> 46.7 KB static.
__global__ void __launch_bounds__(288) k_conv1_tc(const float* __restrict__ x) {
    __shared__ float buf[20 * 584];
    __shared__ float bs[20];
    int blk = blockIdx.x;
    int s = blk / BATCH, b = blk % BATCH;
    int t = threadIdx.x;
    int lane = t & 31, w = t >> 5;
    int g = lane >> 2, tig = lane & 3;

    float* xs = buf;          // 784
    float* Wt = buf + 784;    // 32 x 33 = 1056

    for (int j = t; j < 784; j += 288)
        xs[j] = __uint_as_float(f2tf32(x[b * 784 + j]));
    {
        const float* wp = g_w1p + s * 1024;
        for (int j = t; j < 1024; j += 288)
            Wt[(j >> 5) * 33 + (j & 31)] = wp[j];
    }
    if (t < 20) bs[t] = g_ball[s * NB + t];
    __syncthreads();

    int n0 = w * 64;   // 9 warps cover 576 columns

    int rowbase[8];
#pragma unroll
    for (int nt = 0; nt < 8; nt++) {
        int c = n0 + nt * 8 + g;
        int y = c / 24, xx = c % 24;
        rowbase[nt] = y * 28 + xx;
    }
    int off0[4], off1[4];
#pragma unroll
    for (int kt = 0; kt < 4; kt++) {
        int kk0 = kt * 8 + tig;
        off0[kt] = (kk0 <= 24) ? (kk0 / 5) * 28 + (kk0 % 5) : 0;
        int kk1 = kk0 + 4;
        off1[kt] = (kk1 <= 24) ? (kk1 / 5) * 28 + (kk1 % 5) : 0;
    }

    float acc[2][8][4];
#pragma unroll
    for (int mt = 0; mt < 2; mt++)
#pragma unroll
        for (int nt = 0; nt < 8; nt++)
#pragma unroll
            for (int q = 0; q < 4; q++) acc[mt][nt][q] = 0.0f;

#pragma unroll
    for (int kt = 0; kt < 4; kt++) {
        const float* Wk = Wt + (kt * 8 + tig) * 33;
        uint32_t a[2][4];
#pragma unroll
        for (int mt = 0; mt < 2; mt++) {
            a[mt][0] = __float_as_uint(Wk[mt * 16 + g]);
            a[mt][1] = __float_as_uint(Wk[mt * 16 + 8 + g]);
            a[mt][2] = __float_as_uint(Wk[4 * 33 + mt * 16 + g]);
            a[mt][3] = __float_as_uint(Wk[4 * 33 + mt * 16 + 8 + g]);
        }
#pragma unroll
        for (int nt = 0; nt < 8; nt++) {
            uint32_t br0 = __float_as_uint(xs[rowbase[nt] + off0[kt]]);
            uint32_t br1 = __float_as_uint(xs[rowbase[nt] + off1[kt]]);
#pragma unroll
            for (int mt = 0; mt < 2; mt++) {
                asm volatile(
                    "mma.sync.aligned.m16n8k8.row.col.f32.tf32.tf32.f32 "
                    "{%0,%1,%2,%3}, {%4,%5,%6,%7}, {%8,%9}, {%0,%1,%2,%3};\n"
                    : "+f"(acc[mt][nt][0]), "+f"(acc[mt][nt][1]),
                      "+f"(acc[mt][nt][2]), "+f"(acc[mt][nt][3])
                    : "r"(a[mt][0]), "r"(a[mt][1]), "r"(a[mt][2]), "r"(a[mt][3]),
                      "r"(br0), "r"(br1));
            }
        }
    }

    // epilogue: C -> smem union (all xs/W reads done), then bias+relu+maxpool
    __syncthreads();
    float* Csm = buf;   // [20][584]
#pragma unroll
    for (int mt = 0; mt < 2; mt++) {
        int r0 = mt * 16 + g;
        int r1 = r0 + 8;
#pragma unroll
        for (int nt = 0; nt < 8; nt++) {
            int c0 = n0 + nt * 8 + 2 * tig;
            if (r0 < 20) {
                Csm[r0 * 584 + c0]     = acc[mt][nt][0];
                Csm[r0 * 584 + c0 + 1] = acc[mt][nt][1];
            }
            if (r1 < 20) {
                Csm[r1 * 584 + c0]     = acc[mt][nt][2];
                Csm[r1 * 584 + c0 + 1] = acc[mt][nt][3];
            }
        }
    }
    __syncthreads();

    float* outp = g_h1 + (long)(s * BATCH + b) * 2880;
    for (int idx = t; idx < 2880; idx += 288) {
        int ch = idx / 144, pp = idx % 144;
        int pi = pp / 12, pj = pp % 12;
        int n = (2 * pi) * 24 + 2 * pj;
        float v0 = Csm[ch * 584 + n],      v1 = Csm[ch * 584 + n + 1];
        float v2 = Csm[ch * 584 + n + 24], v3 = Csm[ch * 584 + n + 25];
        float v = fmaxf(fmaxf(v0, v1), fmaxf(v2, v3)) + bs[ch];
        outp[ch * 144 + pp] = fmaxf(v, 0.0f);
    }
}

// ---------------- kernel 3: conv2 tf32 implicit GEMM, direct B gather (R9 config) ----------------
// 8 images/block, 512 threads / 16 warps, warp tile m32 x n64 (2m x 8n).
#define CV2_WF (640 * 52)
#define CV2_IF (8 * 2880)
#define CV2T_SMEM ((CV2_WF + CV2_IF) * 4)

__global__ void __launch_bounds__(512) k_conv2_tc() {
    extern __shared__ float sm[];
    float* Wsm = sm;                 // 33280
    float* ins = sm + CV2_WF;        // 23040
    int blk = blockIdx.x;
    int s = blk >> 4;
    int b0 = (blk & 15) * 8;
    int t = threadIdx.x;
    int lane = t & 31, w = t >> 5;
    int g = lane >> 2, tig = lane & 3;

    {
        const float4* wp = (const float4*)(g_w2p + (long)s * 33280);
        float4* wd = (float4*)Wsm;
        for (int j = t; j < 8320; j += 512) wd[j] = wp[j];
        const float4* ip = (const float4*)(g_h1 + (long)(s * BATCH + b0) * 2880);
        float4* id = (float4*)ins;
        for (int j = t; j < 5760; j += 512) {
            float4 v = ip[j];
            v.x = __uint_as_float(f2tf32(v.x));
            v.y = __uint_as_float(f2tf32(v.y));
            v.z = __uint_as_float(f2tf32(v.z));
            v.w = __uint_as_float(f2tf32(v.w));
            id[j] = v;
        }
    }

    int m0 = (w & 1) * 32;
    int n0 = (w >> 1) * 64;

    int mA[2][2];
#pragma unroll
    for (int mt = 0; mt < 2; mt++) {
        int r0 = m0 + mt * 16 + g;
        int r1 = r0 + 8;
        mA[mt][0] = (r0 < 50) ? r0 : 50;
        mA[mt][1] = (r1 < 50) ? r1 : 50;
    }

    int rowbase[8];
#pragma unroll
    for (int nt = 0; nt < 8; nt++) {
        int c = n0 + nt * 8 + g;
        int img = c >> 6, y = (c >> 3) & 7, xx = c & 7;
        rowbase[nt] = img * 2880 + y * 12 + xx;
    }
    int off0[4], off1[4];
#pragma unroll
    for (int kt = 0; kt < 4; kt++) {
        int kk0 = kt * 8 + tig;
        off0[kt] = (kk0 <= 24) ? (kk0 / 5) * 12 + (kk0 % 5) : 0;
        int kk1 = kk0 + 4;
        off1[kt] = (kk1 <= 24) ? (kk1 / 5) * 12 + (kk1 % 5) : 0;
    }

    float acc[2][8][4];
#pragma unroll
    for (int mt = 0; mt < 2; mt++)
#pragma unroll
        for (int nt = 0; nt < 8; nt++)
#pragma unroll
            for (int q = 0; q < 4; q++) acc[mt][nt][q] = 0.0f;

    __syncthreads();

#pragma unroll 1
    for (int ci = 0; ci < 20; ci++) {
        int cib = ci * 144;
#pragma unroll
        for (int kt = 0; kt < 4; kt++) {
            const float* Wk = Wsm + (ci * 32 + kt * 8 + tig) * 52;
            uint32_t a[2][4];
#pragma unroll
            for (int mt = 0; mt < 2; mt++) {
                a[mt][0] = __float_as_uint(Wk[mA[mt][0]]);
                a[mt][1] = __float_as_uint(Wk[mA[mt][1]]);
                a[mt][2] = __float_as_uint(Wk[4 * 52 + mA[mt][0]]);
                a[mt][3] = __float_as_uint(Wk[4 * 52 + mA[mt][1]]);
            }
            const float* insc = ins + cib;
#pragma unroll
            for (int nt = 0; nt < 8; nt++) {
                uint32_t br0 = __float_as_uint(insc[rowbase[nt] + off0[kt]]);
                uint32_t br1 = __float_as_uint(insc[rowbase[nt] + off1[kt]]);
#pragma unroll
                for (int mt = 0; mt < 2; mt++) {
                    asm volatile(
                        "mma.sync.aligned.m16n8k8.row.col.f32.tf32.tf32.f32 "
                        "{%0,%1,%2,%3}, {%4,%5,%6,%7}, {%8,%9}, {%0,%1,%2,%3};\n"
                        : "+f"(acc[mt][nt][0]), "+f"(acc[mt][nt][1]),
                          "+f"(acc[mt][nt][2]), "+f"(acc[mt][nt][3])
                        : "r"(a[mt][0]), "r"(a[mt][1]), "r"(a[mt][2]), "r"(a[mt][3]),
                          "r"(br0), "r"(br1));
                }
            }
        }
    }

    __syncthreads();
    float* Csm = Wsm;   // [64][520]
#pragma unroll
    for (int mt = 0; mt < 2; mt++) {
        int r0 = m0 + mt * 16 + g;
#pragma unroll
        for (int nt = 0; nt < 8; nt++) {
            int c0 = n0 + nt * 8 + 2 * tig;
            Csm[r0 * 520 + c0]           = acc[mt][nt][0];
            Csm[r0 * 520 + c0 + 1]       = acc[mt][nt][1];
            Csm[(r0 + 8) * 520 + c0]     = acc[mt][nt][2];
            Csm[(r0 + 8) * 520 + c0 + 1] = acc[mt][nt][3];
        }
    }
    __syncthreads();

    for (int idx = t; idx < 6400; idx += 512) {
        int ch = idx >> 7;
        int r = idx & 127;
        int img = r >> 4;
        int pp = r & 15;
        int py = pp >> 2, px = pp & 3;
        int n = img * 64 + (2 * py) * 8 + 2 * px;
        float v0 = Csm[ch * 520 + n],       v1 = Csm[ch * 520 + n + 1];
        float v2 = Csm[ch * 520 + n + 8],   v3 = Csm[ch * 520 + n + 9];
        float v = fmaxf(fmaxf(v0, v1), fmaxf(v2, v3)) + g_ball[s * NB + 20 + ch];
        g_h2[(long)(s * BATCH + b0 + img) * 800 + ch * 16 + pp] = fmaxf(v, 0.0f);
    }
}

// ---------------- kernel 4: fc1 as tf32 tensor-core GEMM ----------------
#define FC1_APAD 44
#define FC1_BPAD 132
__global__ void __launch_bounds__(256) k_fc1_tc(const float* __restrict__ e,
                                                const float* __restrict__ mu_w) {
    __shared__ float As[128 * FC1_APAD];
    __shared__ float Bs[32 * FC1_BPAD];
    int s = blockIdx.y;
    int m0blk = blockIdx.x * 128;
    int t = threadIdx.x;
    int lane = t & 31, w = t >> 5;
    int g = lane >> 2, tig = lane & 3;
    int wm0 = (w & 3) * 32;
    int wn0 = (w >> 2) * 64;

    const float* eb  = e + (long)s * ES + WOFF2;
    const float* mwb = mu_w + WOFF2;
    const float* sgb = g_sigw + WOFF2;
    const float* h2b = g_h2 + (long)s * BATCH * 800;

    float acc[2][8][4];
#pragma unroll
    for (int mt = 0; mt < 2; mt++)
#pragma unroll
        for (int nt = 0; nt < 8; nt++)
#pragma unroll
            for (int q = 0; q < 4; q++) acc[mt][nt][q] = 0.0f;

#pragma unroll 1
    for (int kc = 0; kc < 25; kc++) {
        int k0 = kc * 32;
#pragma unroll
        for (int jj = t; jj < 1024; jj += 256) {
            int m = jj >> 3, kq = jj & 7;
            int grow = m0blk + m;
            float4 v = {0.0f, 0.0f, 0.0f, 0.0f};
            if (grow < 500) {
                long ai = (long)grow * 800 + k0 + kq * 4;
                float4 sg = *(const float4*)(sgb + ai);
                float4 ev = *(const float4*)(eb + ai);
                float4 mv = *(const float4*)(mwb + ai);
                v.x = __uint_as_float(f2tf32(fmaf(sg.x, ev.x, mv.x)));
                v.y = __uint_as_float(f2tf32(fmaf(sg.y, ev.y, mv.y)));
                v.z = __uint_as_float(f2tf32(fmaf(sg.z, ev.z, mv.z)));
                v.w = __uint_as_float(f2tf32(fmaf(sg.w, ev.w, mv.w)));
            }
            *(float4*)(As + m * FC1_APAD + kq * 4) = v;
        }
#pragma unroll
        for (int jj = t; jj < 1024; jj += 256) {
            int n = jj >> 3, kq = jj & 7;
            float4 v = *(const float4*)(h2b + (long)n * 800 + k0 + kq * 4);
            Bs[(kq * 4 + 0) * FC1_BPAD + n] = __uint_as_float(f2tf32(v.x));
            Bs[(kq * 4 + 1) * FC1_BPAD + n] = __uint_as_float(f2tf32(v.y));
            Bs[(kq * 4 + 2) * FC1_BPAD + n] = __uint_as_float(f2tf32(v.z));
            Bs[(kq * 4 + 3) * FC1_BPAD + n] = __uint_as_float(f2tf32(v.w));
        }
        __syncthreads();

#pragma unroll
        for (int kt = 0; kt < 4; kt++) {
            uint32_t a[2][4];
#pragma unroll
            for (int mt = 0; mt < 2; mt++) {
                const float* Ar = As + (wm0 + mt * 16 + g) * FC1_APAD + kt * 8 + tig;
                a[mt][0] = __float_as_uint(Ar[0]);
                a[mt][1] = __float_as_uint(Ar[8 * FC1_APAD]);
                a[mt][2] = __float_as_uint(Ar[4]);
                a[mt][3] = __float_as_uint(Ar[8 * FC1_APAD + 4]);
            }
            const float* Bk = Bs + (kt * 8 + tig) * FC1_BPAD + wn0 + g;
#pragma unroll
            for (int nt = 0; nt < 8; nt++) {
                uint32_t br0 = __float_as_uint(Bk[nt * 8]);
                uint32_t br1 = __float_as_uint(Bk[4 * FC1_BPAD + nt * 8]);
#pragma unroll
                for (int mt = 0; mt < 2; mt++) {
                    asm volatile(
                        "mma.sync.aligned.m16n8k8.row.col.f32.tf32.tf32.f32 "
                        "{%0,%1,%2,%3}, {%4,%5,%6,%7}, {%8,%9}, {%0,%1,%2,%3};\n"
                        : "+f"(acc[mt][nt][0]), "+f"(acc[mt][nt][1]),
                          "+f"(acc[mt][nt][2]), "+f"(acc[mt][nt][3])
                        : "r"(a[mt][0]), "r"(a[mt][1]), "r"(a[mt][2]), "r"(a[mt][3]),
                          "r"(br0), "r"(br1));
                }
            }
        }
        __syncthreads();
    }

#pragma unroll
    for (int mt = 0; mt < 2; mt++) {
#pragma unroll
        for (int half = 0; half < 2; half++) {
            int m = m0blk + wm0 + mt * 16 + half * 8 + g;
            if (m < 500) {
                float bias = g_ball[s * NB + 70 + m];
                float* op = g_h3 + ((long)s * 500 + m) * BATCH;
#pragma unroll
                for (int nt = 0; nt < 8; nt++) {
                    int c0 = wn0 + nt * 8 + 2 * tig;
                    op[c0]     = fmaxf(acc[mt][nt][half * 2]     + bias, 0.0f);
                    op[c0 + 1] = fmaxf(acc[mt][nt][half * 2 + 1] + bias, 0.0f);
                }
            }
        }
    }
}

// ---------------- kernel 5: fc2 + bias + log_softmax ----------------
__global__ void __launch_bounds__(128) k_fc2(const float* __restrict__ e,
                                             const float* __restrict__ mu_w) {
    __shared__ float ws[5000];
    __shared__ float bs[10];
    int s = blockIdx.x;
    int t = threadIdx.x;
    for (int j = t; j < 5000; j += 128) {
        long gi = (long)WOFF3 + j;
        ws[j] = fmaf(g_sigw[gi], e[(long)s * ES + gi], mu_w[gi]);
    }
    if (t < 10) bs[t] = g_ball[s * NB + 570 + t];
    __syncthreads();

    float acc[10];
#pragma unroll
    for (int o = 0; o < 10; o++) acc[o] = bs[o];

    const float* hp = g_h3 + (long)s * 500 * BATCH + t;
    for (int i = 0; i < 500; i++) {
        float v = hp[(long)i * BATCH];
#pragma unroll
        for (int o = 0; o < 10; o++) acc[o] = fmaf(ws[o * 500 + i], v, acc[o]);
    }

    float m = acc[0];
#pragma unroll
    for (int o = 1; o < 10; o++) m = fmaxf(m, acc[o]);
    float sum = 0.0f;
#pragma unroll
    for (int o = 0; o < 10; o++) sum += expf(acc[o] - m);
    float lse = m + logf(sum);

    float* op = g_lsm + ((long)s * BATCH + t) * 10;
#pragma unroll
    for (int o = 0; o < 10; o++) op[o] = acc[o] - lse;
}

// ---------------- kernel 6: deterministic mean over samples ----------------
__global__ void k_reduce(float* __restrict__ out) {
    int idx = blockIdx.x * blockDim.x + threadIdx.x;
    if (idx >= BATCH * 10) return;
    int b = idx / 10, o = idx % 10;
    float acc = 0.0f;
    for (int s = 0; s < S; s++) acc += g_lsm[((long)s * BATCH + b) * 10 + o];
    out[idx] = acc * (1.0f / (float)S);
}

// ---------------- launch ----------------
extern "C" void kernel_launch(void* const* d_in, const int* in_sizes, int n_in,
                              void* d_out, int out_size) {
    const float* x     = (const float*)d_in[0];
    const float* e     = (const float*)d_in[1];
    const float* mu_w  = (const float*)d_in[2];
    const float* rho_w = (const float*)d_in[3];
    const float* mu_b  = (const float*)d_in[4];
    const float* rho_b = (const float*)d_in[5];
    float* out = (float*)d_out;

    static int smem_set = 0;
    if (!smem_set) {
        cudaFuncSetAttribute(k_conv2_tc, cudaFuncAttributeMaxDynamicSharedMemorySize,
                             CV2T_SMEM);
        smem_set = 1;
    }

    k_sig<<<(ES + 255) / 256, 256>>>(rho_w, rho_b);

    int wb_total = S * W12N + S * NB;
    k_wb<<<(wb_total + 255) / 256, 256>>>(e, mu_w, mu_b);

    k_conv1_tc<<<S * BATCH, 288>>>(x);
    k_conv2_tc<<<S * 16, 512, CV2T_SMEM>>>();

    dim3 g1(4, S);
    k_fc1_tc<<<g1, 256>>>(e, mu_w);
    k_fc2<<<S, 128>>>(e, mu_w);
    k_reduce<<<10, 128>>>(out);
}

// round 16
// speedup vs baseline: 1.7099x; 1.7099x over previous
#include <cuda_runtime.h>
#include <cuda_bf16.h>
#include <math.h>
#include <stdint.h>

#define S 100
#define BATCH 128
#define NW 430500
#define NB 580
#define ES (NW + NB)
#define W12N 25500
#define WOFF2 25500
#define WOFF3 425500

// ---------------- scratch (device globals; no runtime allocation) ----------------
__device__ float g_sigw[NW];
__device__ float g_sigb[NB];
__device__ float g_w1[S * 500];                // per-sample conv1 weights (fp32)
__device__ __nv_bfloat16 g_w2pb[S * 33280];    // conv2 weights [k=ci*32+kk][52 ch pad], bf16; pads zero
__device__ float g_ball[S * NB];               // per-sample all biases
__device__ float g_h1[S * BATCH * 2880];       // after conv1+relu+pool
__device__ float g_h2[S * BATCH * 800];        // after conv2+relu+pool
__device__ float g_h3[S * 500 * BATCH];        // after fc1+relu: [s][500][128]
__device__ float g_lsm[S * BATCH * 10];        // per-sample log-softmax

__device__ __forceinline__ float softplusf(float r) {
    return fmaxf(r, 0.0f) + log1pf(expf(-fabsf(r)));
}

__device__ __forceinline__ uint32_t f2tf32(float v) {
    uint32_t o;
    asm("cvt.rna.tf32.f32 %0, %1;" : "=r"(o) : "f"(v));
    return o;
}

// ---------------- kernel 0: softplus(rho) ----------------
__global__ void k_sig(const float* __restrict__ rho_w, const float* __restrict__ rho_b) {
    int i = blockIdx.x * blockDim.x + threadIdx.x;
    if (i < NW) g_sigw[i] = softplusf(rho_w[i]);
    else if (i < NW + NB) g_sigb[i - NW] = softplusf(rho_b[i - NW]);
}

// ---------------- kernel 1: materialize conv weights + biases ----------------
// conv1 -> g_w1 (fp32). conv2 -> g_w2pb bf16 [(ci*32+wo)*52 + ch]; pads stay zero.
__global__ void k_wb(const float* __restrict__ e,
                     const float* __restrict__ mu_w,
                     const float* __restrict__ mu_b) {
    int i = blockIdx.x * blockDim.x + threadIdx.x;
    if (i < S * W12N) {
        int s = i / W12N, j = i % W12N;
        float v = fmaf(g_sigw[j], e[(long)s * ES + j], mu_w[j]);
        if (j < 500) {
            g_w1[s * 500 + j] = v;
        } else {
            int jj = j - 500;
            int ch = jj / 500;
            int r = jj % 500;
            int ci = r / 25, wo = r % 25;
            g_w2pb[(long)s * 33280 + (ci * 32 + wo) * 52 + ch] = __float2bfloat16(v);
        }
    } else {
        int r = i - S * W12N;
        if (r < S * NB) {
            int s = r / NB, j = r % NB;
            g_ball[r] = fmaf(g_sigb[j], e[(long)s * ES + NW + j], mu_b[j]);
        }
    }
}

// ---------------- kernel 2: conv1 + bias + relu + maxpool (scalar, proven) ----------------
__global__ void __launch_bounds__(288) k_conv1(const float* __restrict__ x) {
    __shared__ float xs[784];
    __shared__ float ws[500];
    __shared__ float bs[20];
    int blk = blockIdx.x;
    int s = blk / BATCH, b = blk % BATCH;
    int t = threadIdx.x;
    for (int j = t; j < 784; j += 288) xs[j] = x[b * 784 + j];
    for (int j = t; j < 500; j += 288) ws[j] = g_w1[s * 500 + j];
    if (t < 20) bs[t] = g_ball[s * NB + t];
    __syncthreads();

    int pp = t % 144, cg = t / 144;
    int pi = pp / 12, pj = pp % 12;
    float acc[10][4];
#pragma unroll
    for (int k = 0; k < 10; k++) { acc[k][0] = acc[k][1] = acc[k][2] = acc[k][3] = 0.0f; }

    const float* xb = xs + (2 * pi) * 28 + 2 * pj;
#pragma unroll 1
    for (int ky = 0; ky < 5; ky++) {
#pragma unroll
        for (int kx = 0; kx < 5; kx++) {
            float i00 = xb[ky * 28 + kx];
            float i01 = xb[ky * 28 + kx + 1];
            float i10 = xb[(ky + 1) * 28 + kx];
            float i11 = xb[(ky + 1) * 28 + kx + 1];
#pragma unroll
            for (int k = 0; k < 10; k++) {
                float wv = ws[(cg * 10 + k) * 25 + ky * 5 + kx];
                acc[k][0] = fmaf(wv, i00, acc[k][0]);
                acc[k][1] = fmaf(wv, i01, acc[k][1]);
                acc[k][2] = fmaf(wv, i10, acc[k][2]);
                acc[k][3] = fmaf(wv, i11, acc[k][3]);
            }
        }
    }
    float* outp = g_h1 + (long)(s * BATCH + b) * 2880;
#pragma unroll
    for (int k = 0; k < 10; k++) {
        int c = cg * 10 + k;
        float v = fmaxf(fmaxf(acc[k][0], acc[k][1]), fmaxf(acc[k][2], acc[k][3])) + bs[c];
        outp[c * 144 + pp] = fmaxf(v, 0.0f);
    }
}

// ---------------- kernel 3: conv2 implicit GEMM, bf16 weights, 2 CTAs/SM ----------------
// 4 images/block, 256 threads / 8 warps, warp tile m32 x n64 (2m x 4n).
// C[64][256] = W[64][640](bf16->fp32) x col[640][256](tf32 gather).
// smem: W bf16 [640][52] = 66560 B + input 4*2880 fp32 = 46080 B -> 110 KB => 2 CTAs/SM.
#define CV2_WB 66560
#define CV2_IF (4 * 2880)
#define CV2T_SMEM (CV2_WB + CV2_IF * 4)
#define CSTRIDE2 264

__global__ void __launch_bounds__(256, 2) k_conv2_tc() {
    extern __shared__ float sm[];
    uint16_t* Wsm = (uint16_t*)sm;            // 33280 bf16
    float* ins = sm + CV2_WB / 4;             // 11520 floats
    int blk = blockIdx.x;
    int s = blk >> 5;
    int b0 = (blk & 31) * 4;
    int t = threadIdx.x;
    int lane = t & 31, w = t >> 5;
    int g = lane >> 2, tig = lane & 3;

    // cooperative loads (weights bf16 verbatim; input tf32-rounded)
    {
        const uint4* wp = (const uint4*)(g_w2pb + (long)s * 33280);
        uint4* wd = (uint4*)Wsm;
        for (int j = t; j < 4160; j += 256) wd[j] = wp[j];
        const float4* ip = (const float4*)(g_h1 + (long)(s * BATCH + b0) * 2880);
        float4* id = (float4*)ins;
        for (int j = t; j < 2880; j += 256) {
            float4 v = ip[j];
            v.x = __uint_as_float(f2tf32(v.x));
            v.y = __uint_as_float(f2tf32(v.y));
            v.z = __uint_as_float(f2tf32(v.z));
            v.w = __uint_as_float(f2tf32(v.w));
            id[j] = v;
        }
    }

    int m0 = (w & 1) * 32;
    int n0 = (w >> 1) * 64;

    // A row indices (clamp to zero column 50 for rows >= 50)
    int mA[2][2];
#pragma unroll
    for (int mt = 0; mt < 2; mt++) {
        int r0 = m0 + mt * 16 + g;
        int r1 = r0 + 8;
        mA[mt][0] = (r0 < 50) ? r0 : 50;
        mA[mt][1] = (r1 < 50) ? r1 : 50;
    }

    // B gather bases: column c = n0 + nt*8 + g -> (img, y, x)
    int rowbase[8];
#pragma unroll
    for (int nt = 0; nt < 8; nt++) {
        int c = n0 + nt * 8 + g;
        int img = c >> 6, y = (c >> 3) & 7, xx = c & 7;
        rowbase[nt] = img * 2880 + y * 12 + xx;
    }
    int off0[4], off1[4];
#pragma unroll
    for (int kt = 0; kt < 4; kt++) {
        int kk0 = kt * 8 + tig;
        off0[kt] = (kk0 <= 24) ? (kk0 / 5) * 12 + (kk0 % 5) : 0;
        int kk1 = kk0 + 4;
        off1[kt] = (kk1 <= 24) ? (kk1 / 5) * 12 + (kk1 % 5) : 0;
    }

    float acc[2][8][4];
#pragma unroll
    for (int mt = 0; mt < 2; mt++)
#pragma unroll
        for (int nt = 0; nt < 8; nt++)
#pragma unroll
            for (int q = 0; q < 4; q++) acc[mt][nt][q] = 0.0f;

    __syncthreads();

#pragma unroll 1
    for (int ci = 0; ci < 20; ci++) {
        int cib = ci * 144;
#pragma unroll
        for (int kt = 0; kt < 4; kt++) {
            const uint16_t* Wk = Wsm + (ci * 32 + kt * 8 + tig) * 52;
            uint32_t a[2][4];
#pragma unroll
            for (int mt = 0; mt < 2; mt++) {
                a[mt][0] = ((uint32_t)Wk[mA[mt][0]]) << 16;
                a[mt][1] = ((uint32_t)Wk[mA[mt][1]]) << 16;
                a[mt][2] = ((uint32_t)Wk[4 * 52 + mA[mt][0]]) << 16;
                a[mt][3] = ((uint32_t)Wk[4 * 52 + mA[mt][1]]) << 16;
            }
            const float* insc = ins + cib;
#pragma unroll
            for (int nt = 0; nt < 8; nt++) {
                uint32_t br0 = __float_as_uint(insc[rowbase[nt] + off0[kt]]);
                uint32_t br1 = __float_as_uint(insc[rowbase[nt] + off1[kt]]);
#pragma unroll
                for (int mt = 0; mt < 2; mt++) {
                    asm volatile(
                        "mma.sync.aligned.m16n8k8.row.col.f32.tf32.tf32.f32 "
                        "{%0,%1,%2,%3}, {%4,%5,%6,%7}, {%8,%9}, {%0,%1,%2,%3};\n"
                        : "+f"(acc[mt][nt][0]), "+f"(acc[mt][nt][1]),
                          "+f"(acc[mt][nt][2]), "+f"(acc[mt][nt][3])
                        : "r"(a[mt][0]), "r"(a[mt][1]), "r"(a[mt][2]), "r"(a[mt][3]),
                          "r"(br0), "r"(br1));
                }
            }
        }
    }

    // epilogue: C -> smem (reuse whole smem; all W/input reads done), bias+relu+maxpool
    __syncthreads();
    float* Csm = sm;   // [64][CSTRIDE2] = 67.6 KB < 110 KB
#pragma unroll
    for (int mt = 0; mt < 2; mt++) {
        int r0 = m0 + mt * 16 + g;
#pragma unroll
        for (int nt = 0; nt < 8; nt++) {
            int c0 = n0 + nt * 8 + 2 * tig;
            Csm[r0 * CSTRIDE2 + c0]           = acc[mt][nt][0];
            Csm[r0 * CSTRIDE2 + c0 + 1]       = acc[mt][nt][1];
            Csm[(r0 + 8) * CSTRIDE2 + c0]     = acc[mt][nt][2];
            Csm[(r0 + 8) * CSTRIDE2 + c0 + 1] = acc[mt][nt][3];
        }
    }
    __syncthreads();

    for (int idx = t; idx < 3200; idx += 256) {
        int ch = idx >> 6;        // 50 channels x (4 img x 16 pooled px)
        int r = idx & 63;
        int img = r >> 4;
        int pp = r & 15;
        int py = pp >> 2, px = pp & 3;
        int n = img * 64 + (2 * py) * 8 + 2 * px;
        float v0 = Csm[ch * CSTRIDE2 + n],     v1 = Csm[ch * CSTRIDE2 + n + 1];
        float v2 = Csm[ch * CSTRIDE2 + n + 8], v3 = Csm[ch * CSTRIDE2 + n + 9];
        float v = fmaxf(fmaxf(v0, v1), fmaxf(v2, v3)) + g_ball[s * NB + 20 + ch];
        g_h2[(long)(s * BATCH + b0 + img) * 800 + ch * 16 + pp] = fmaxf(v, 0.0f);
    }
}

// ---------------- kernel 4: fc1 as tf32 tensor-core GEMM ----------------
#define FC1_APAD 44
#define FC1_BPAD 132
__global__ void __launch_bounds__(256) k_fc1_tc(const float* __restrict__ e,
                                                const float* __restrict__ mu_w) {
    __shared__ float As[128 * FC1_APAD];
    __shared__ float Bs[32 * FC1_BPAD];
    int s = blockIdx.y;
    int m0blk = blockIdx.x * 128;
    int t = threadIdx.x;
    int lane = t & 31, w = t >> 5;
    int g = lane >> 2, tig = lane & 3;
    int wm0 = (w & 3) * 32;
    int wn0 = (w >> 2) * 64;

    const float* eb  = e + (long)s * ES + WOFF2;
    const float* mwb = mu_w + WOFF2;
    const float* sgb = g_sigw + WOFF2;
    const float* h2b = g_h2 + (long)s * BATCH * 800;

    float acc[2][8][4];
#pragma unroll
    for (int mt = 0; mt < 2; mt++)
#pragma unroll
        for (int nt = 0; nt < 8; nt++)
#pragma unroll
            for (int q = 0; q < 4; q++) acc[mt][nt][q] = 0.0f;

#pragma unroll 1
    for (int kc = 0; kc < 25; kc++) {
        int k0 = kc * 32;
#pragma unroll
        for (int jj = t; jj < 1024; jj += 256) {
            int m = jj >> 3, kq = jj & 7;
            int grow = m0blk + m;
            float4 v = {0.0f, 0.0f, 0.0f, 0.0f};
            if (grow < 500) {
                long ai = (long)grow * 800 + k0 + kq * 4;
                float4 sg = *(const float4*)(sgb + ai);
                float4 ev = *(const float4*)(eb + ai);
                float4 mv = *(const float4*)(mwb + ai);
                v.x = __uint_as_float(f2tf32(fmaf(sg.x, ev.x, mv.x)));
                v.y = __uint_as_float(f2tf32(fmaf(sg.y, ev.y, mv.y)));
                v.z = __uint_as_float(f2tf32(fmaf(sg.z, ev.z, mv.z)));
                v.w = __uint_as_float(f2tf32(fmaf(sg.w, ev.w, mv.w)));
            }
            *(float4*)(As + m * FC1_APAD + kq * 4) = v;
        }
#pragma unroll
        for (int jj = t; jj < 1024; jj += 256) {
            int n = jj >> 3, kq = jj & 7;
            float4 v = *(const float4*)(h2b + (long)n * 800 + k0 + kq * 4);
            Bs[(kq * 4 + 0) * FC1_BPAD + n] = __uint_as_float(f2tf32(v.x));
            Bs[(kq * 4 + 1) * FC1_BPAD + n] = __uint_as_float(f2tf32(v.y));
            Bs[(kq * 4 + 2) * FC1_BPAD + n] = __uint_as_float(f2tf32(v.z));
            Bs[(kq * 4 + 3) * FC1_BPAD + n] = __uint_as_float(f2tf32(v.w));
        }
        __syncthreads();

#pragma unroll
        for (int kt = 0; kt < 4; kt++) {
            uint32_t a[2][4];
#pragma unroll
            for (int mt = 0; mt < 2; mt++) {
                const float* Ar = As + (wm0 + mt * 16 + g) * FC1_APAD + kt * 8 + tig;
                a[mt][0] = __float_as_uint(Ar[0]);
                a[mt][1] = __float_as_uint(Ar[8 * FC1_APAD]);
                a[mt][2] = __float_as_uint(Ar[4]);
                a[mt][3] = __float_as_uint(Ar[8 * FC1_APAD + 4]);
            }
            const float* Bk = Bs + (kt * 8 + tig) * FC1_BPAD + wn0 + g;
#pragma unroll
            for (int nt = 0; nt < 8; nt++) {
                uint32_t br0 = __float_as_uint(Bk[nt * 8]);
                uint32_t br1 = __float_as_uint(Bk[4 * FC1_BPAD + nt * 8]);
#pragma unroll
                for (int mt = 0; mt < 2; mt++) {
                    asm volatile(
                        "mma.sync.aligned.m16n8k8.row.col.f32.tf32.tf32.f32 "
                        "{%0,%1,%2,%3}, {%4,%5,%6,%7}, {%8,%9}, {%0,%1,%2,%3};\n"
                        : "+f"(acc[mt][nt][0]), "+f"(acc[mt][nt][1]),
                          "+f"(acc[mt][nt][2]), "+f"(acc[mt][nt][3])
                        : "r"(a[mt][0]), "r"(a[mt][1]), "r"(a[mt][2]), "r"(a[mt][3]),
                          "r"(br0), "r"(br1));
                }
            }
        }
        __syncthreads();
    }

#pragma unroll
    for (int mt = 0; mt < 2; mt++) {
#pragma unroll
        for (int half = 0; half < 2; half++) {
            int m = m0blk + wm0 + mt * 16 + half * 8 + g;
            if (m < 500) {
                float bias = g_ball[s * NB + 70 + m];
                float* op = g_h3 + ((long)s * 500 + m) * BATCH;
#pragma unroll
                for (int nt = 0; nt < 8; nt++) {
                    int c0 = wn0 + nt * 8 + 2 * tig;
                    op[c0]     = fmaxf(acc[mt][nt][half * 2]     + bias, 0.0f);
                    op[c0 + 1] = fmaxf(acc[mt][nt][half * 2 + 1] + bias, 0.0f);
                }
            }
        }
    }
}

// ---------------- kernel 5: fc2 + bias + log_softmax ----------------
__global__ void __launch_bounds__(128) k_fc2(const float* __restrict__ e,
                                             const float* __restrict__ mu_w) {
    __shared__ float ws[5000];
    __shared__ float bs[10];
    int s = blockIdx.x;
    int t = threadIdx.x;
    for (int j = t; j < 5000; j += 128) {
        long gi = (long)WOFF3 + j;
        ws[j] = fmaf(g_sigw[gi], e[(long)s * ES + gi], mu_w[gi]);
    }
    if (t < 10) bs[t] = g_ball[s * NB + 570 + t];
    __syncthreads();

    float acc[10];
#pragma unroll
    for (int o = 0; o < 10; o++) acc[o] = bs[o];

    const float* hp = g_h3 + (long)s * 500 * BATCH + t;
    for (int i = 0; i < 500; i++) {
        float v = hp[(long)i * BATCH];
#pragma unroll
        for (int o = 0; o < 10; o++) acc[o] = fmaf(ws[o * 500 + i], v, acc[o]);
    }

    float m = acc[0];
#pragma unroll
    for (int o = 1; o < 10; o++) m = fmaxf(m, acc[o]);
    float sum = 0.0f;
#pragma unroll
    for (int o = 0; o < 10; o++) sum += expf(acc[o] - m);
    float lse = m + logf(sum);

    float* op = g_lsm + ((long)s * BATCH + t) * 10;
#pragma unroll
    for (int o = 0; o < 10; o++) op[o] = acc[o] - lse;
}

// ---------------- kernel 6: deterministic mean over samples ----------------
__global__ void k_reduce(float* __restrict__ out) {
    int idx = blockIdx.x * blockDim.x + threadIdx.x;
    if (idx >= BATCH * 10) return;
    int b = idx / 10, o = idx % 10;
    float acc = 0.0f;
    for (int s = 0; s < S; s++) acc += g_lsm[((long)s * BATCH + b) * 10 + o];
    out[idx] = acc * (1.0f / (float)S);
}

// ---------------- launch ----------------
extern "C" void kernel_launch(void* const* d_in, const int* in_sizes, int n_in,
                              void* d_out, int out_size) {
    const float* x     = (const float*)d_in[0];
    const float* e     = (const float*)d_in[1];
    const float* mu_w  = (const float*)d_in[2];
    const float* rho_w = (const float*)d_in[3];
    const float* mu_b  = (const float*)d_in[4];
    const float* rho_b = (const float*)d_in[5];
    float* out = (float*)d_out;

    static int smem_set = 0;
    if (!smem_set) {
        cudaFuncSetAttribute(k_conv2_tc, cudaFuncAttributeMaxDynamicSharedMemorySize,
                             CV2T_SMEM);
        smem_set = 1;
    }

    k_sig<<<(ES + 255) / 256, 256>>>(rho_w, rho_b);

    int wb_total = S * W12N + S * NB;
    k_wb<<<(wb_total + 255) / 256, 256>>>(e, mu_w, mu_b);

    k_conv1<<<S * BATCH, 288>>>(x);
    k_conv2_tc<<<S * 32, 256, CV2T_SMEM>>>();

    dim3 g1(4, S);
    k_fc1_tc<<<g1, 256>>>(e, mu_w);
    k_fc2<<<S, 128>>>(e, mu_w);
    k_reduce<<<10, 128>>>(out);
}